// round 12
// baseline (speedup 1.0000x reference)
#include <cuda_runtime.h>

#define GRID 128
#define TPB  512

// cross-block scratch (allocation-free rule: __device__ globals)
__device__ float g_Cpart[GRID];
__device__ float g_upart[GRID * 128];
__device__ unsigned g_cnt = 0;
__device__ unsigned g_gen = 0;

// Grid barrier with scoped release/acquire (no full __threadfence -> no CCTL.IVALL
// L1D flush). 128 CTAs of 512 threads = single wave (<=148 SMs), so all blocks are
// co-resident: spin cannot deadlock. Counters never feed the output (deterministic).
__device__ __forceinline__ void gridbar() {
    __syncthreads();
    if (threadIdx.x == 0) {
        unsigned g;
        asm volatile("ld.relaxed.gpu.global.u32 %0, [%1];" : "=r"(g) : "l"(&g_gen));
        unsigned old;
        asm volatile("atom.acq_rel.gpu.global.add.u32 %0, [%1], %2;"
                     : "=r"(old) : "l"(&g_cnt), "r"(1u) : "memory");
        if (old == GRID - 1) {
            asm volatile("st.relaxed.gpu.global.u32 [%0], %1;" :: "l"(&g_cnt), "r"(0u) : "memory");
            asm volatile("st.release.gpu.global.u32 [%0], %1;" :: "l"(&g_gen), "r"(g + 1) : "memory");
        } else {
            unsigned cur;
            do {
                asm volatile("ld.acquire.gpu.global.u32 %0, [%1];"
                             : "=r"(cur) : "l"(&g_gen) : "memory");
            } while (cur == g);
        }
    }
    __syncthreads();
}

__device__ __forceinline__ float dot4(float4 a, float4 b, float acc) {
    return fmaf(a.x, b.x, fmaf(a.y, b.y, fmaf(a.z, b.z, fmaf(a.w, b.w, acc))));
}

__global__ void __launch_bounds__(TPB, 1)
gcn_fused(const float4* __restrict__ x4,
          const float* __restrict__ adj_w,
          const float* __restrict__ adj_b_p,
          const float4* __restrict__ weight4,
          const float4* __restrict__ bias4,
          float* __restrict__ out) {
    const int t     = threadIdx.x;
    const int blk   = blockIdx.x;
    const int batch = blk >> 5;          // 32 blocks (4096 rows) per batch

    __shared__ float sx[128 * 64];       // x tile, 32 KB, global-read happens ONCE
    __shared__ float sW[4096];           // weight, prefetched phase 0
    __shared__ float sB[64];
    __shared__ float s_sr[128], s_sc[128];
    __shared__ float s_e1[128], s_d[128], s_w2[128];
    __shared__ float red[512];
    __shared__ float su[128], sT[128];
    __shared__ float ws[16];

    // ---------------- Phase 0+1: loads + row dots + C partial --------------
    const float ab = __ldg(adj_b_p);     // issue early
    {
        const int quad = t & 3;          // 4 lanes per row (16 floats each)
        const int r    = t >> 2;         // 0..127
        const int row  = blk * 128 + r;

        // x tile loads first (critical path)
        const float4* xr = x4 + (size_t)row * 16 + quad * 4;
        float4 v0 = xr[0], v1 = xr[1], v2 = xr[2], v3 = xr[3];

        // prefetch weight + bias into smem (needed only after barrier 2)
        ((float4*)sW)[t]       = weight4[t];
        ((float4*)sW)[512 + t] = weight4[512 + t];
        if (t < 16) ((float4*)sB)[t] = bias4[t];

        const float4* w4 = (const float4*)adj_w;
        float4 wc0 = w4[quad * 4 + 0], wc1 = w4[quad * 4 + 1];
        float4 wc2 = w4[quad * 4 + 2], wc3 = w4[quad * 4 + 3];
        float4 wr0 = w4[16 + quad * 4 + 0], wr1 = w4[16 + quad * 4 + 1];
        float4 wr2 = w4[16 + quad * 4 + 2], wr3 = w4[16 + quad * 4 + 3];

        float4* sxr = (float4*)(sx + r * 64 + quad * 16);
        sxr[0] = v0; sxr[1] = v1; sxr[2] = v2; sxr[3] = v3;

        float sc = dot4(v3, wc3, dot4(v2, wc2, dot4(v1, wc1, dot4(v0, wc0, 0.f))));
        float sr = dot4(v3, wr3, dot4(v2, wr2, dot4(v1, wr1, dot4(v0, wr0, 0.f))));
        sc += __shfl_xor_sync(0xffffffffu, sc, 1);
        sc += __shfl_xor_sync(0xffffffffu, sc, 2);
        sr += __shfl_xor_sync(0xffffffffu, sr, 1);
        sr += __shfl_xor_sync(0xffffffffu, sr, 2);
        if (quad == 0) { s_sr[r] = sr; s_sc[r] = sc; }

        float p = (quad == 0) ? sc : 0.f;
        p += __shfl_xor_sync(0xffffffffu, p, 4);
        p += __shfl_xor_sync(0xffffffffu, p, 8);
        p += __shfl_xor_sync(0xffffffffu, p, 16);
        if ((t & 31) == 0) ws[t >> 5] = p;
        __syncthreads();
        if (t == 0) {
            float s = 0.f;
#pragma unroll
            for (int w = 0; w < 16; w++) s += ws[w];
            __stcg(&g_Cpart[blk], s);
        }
    }
    gridbar();   // barrier 1: this batch's C partials in L2

    // ---------------- Phase 2: d per row, u1/u2 partials --------------------
    {
        // Only warps 0-3 need C: redundant per-warp fold, no extra sync.
        if (t < 128) {
            float p = __ldcg(&g_Cpart[batch * 32 + (t & 31)]);
            p += __shfl_xor_sync(0xffffffffu, p, 16);
            p += __shfl_xor_sync(0xffffffffu, p, 8);
            p += __shfl_xor_sync(0xffffffffu, p, 4);
            p += __shfl_xor_sync(0xffffffffu, p, 2);
            p += __shfl_xor_sync(0xffffffffu, p, 1);   // C in all lanes
            const float srv = s_sr[t] + ab;
            const float d = rsqrtf(fmaxf(fmaf(4096.f, srv, p), 1.0f));
            s_e1[t] = d * srv;          // feeds output: e1*T1
            s_d[t]  = d;                // feeds output + u1 weight
            s_w2[t] = s_sc[t] * d;      // u2 weight
        }
        __syncthreads();

        const int f   = t & 63;
        const int sub = t >> 6;          // 8 row-lanes
        float a1 = 0.f, a2 = 0.f;
#pragma unroll
        for (int k = 0; k < 16; k++) {
            const int r = sub + (k << 3);
            const float xv = sx[r * 64 + f];
            a1 = fmaf(s_d[r],  xv, a1);
            a2 = fmaf(s_w2[r], xv, a2);
        }
        red[t] = a1;
        __syncthreads();
        if (t < 64) {
            float s1 = 0.f;
#pragma unroll
            for (int k = 0; k < 8; k++) s1 += red[t + 64 * k];
            __stcg(&g_upart[blk * 128 + t], s1);
        }
        __syncthreads();
        red[t] = a2;
        __syncthreads();
        if (t < 64) {
            float s2 = 0.f;
#pragma unroll
            for (int k = 0; k < 8; k++) s2 += red[t + 64 * k];
            __stcg(&g_upart[blk * 128 + 64 + t], s2);
        }
    }
    gridbar();   // barrier 2: this batch's u partials in L2

    // ---------------- Phase 3: fold u, matvec T, stream output -------------
    {
        // fold 32 u-partials (16 KB, L2-hot): 8 ldcg per thread
        const int e  = t & 127;
        const int g4 = t >> 7;           // 4 groups of 8 partials
        float acc = 0.f;
#pragma unroll
        for (int k = 0; k < 8; k++)
            acc += __ldcg(&g_upart[(batch * 32 + g4 * 8 + k) * 128 + e]);
        red[t] = acc;
        __syncthreads();
        if (t < 128)
            su[t] = red[t] + red[128 + t] + red[256 + t] + red[384 + t];
        __syncthreads();

        // split-K matvec: 4 threads per (which,o) pair, 16-FMA chains
        {
            const int pair  = t & 127;
            const int which = pair >> 6, o = pair & 63;
            const int split = t >> 7;            // 0..3
            const float* u = &su[which * 64 + split * 16];
            const float* w = &sW[split * 16 * 64 + o];
            float p = 0.f;
#pragma unroll
            for (int ff = 0; ff < 16; ff++)
                p = fmaf(u[ff], w[ff * 64], p);
            red[t] = p;
        }
        __syncthreads();
        if (t < 128)
            sT[t] = (red[t] + red[128 + t]) + (red[256 + t] + red[384 + t]);
        __syncthreads();

        // output: thread t handles row r, 16 consecutive o's (4 float4 stores)
        const int r = t >> 2, q = t & 3;
        const float e1 = s_e1[r];
        const float dd = s_d[r];
        const float4* T1p = (const float4*)&sT[q * 16];
        const float4* T2p = (const float4*)&sT[64 + q * 16];
        const float4* Bp  = (const float4*)&sB[q * 16];
        float4* op = (float4*)&out[(size_t)((blk * 128 + r) << 6) + q * 16];
#pragma unroll
        for (int i = 0; i < 4; i++) {
            const float4 t1 = T1p[i], t2 = T2p[i], bb = Bp[i];
            float4 v;
            v.x = fmaxf(fmaf(e1, t1.x, fmaf(dd, t2.x, bb.x)), 0.f);
            v.y = fmaxf(fmaf(e1, t1.y, fmaf(dd, t2.y, bb.y)), 0.f);
            v.z = fmaxf(fmaf(e1, t1.z, fmaf(dd, t2.z, bb.z)), 0.f);
            v.w = fmaxf(fmaf(e1, t1.w, fmaf(dd, t2.w, bb.w)), 0.f);
            op[i] = v;
        }
    }
}

extern "C" void kernel_launch(void* const* d_in, const int* in_sizes, int n_in,
                              void* d_out, int out_size) {
    const float* x = nullptr;       // 1048576
    const float* adj_w = nullptr;   // 128
    const float* adj_b = nullptr;   // 1
    const float* weight = nullptr;  // 4096
    const float* bias = nullptr;    // 64
    for (int i = 0; i < n_in; i++) {
        switch (in_sizes[i]) {
            case 1048576: x      = (const float*)d_in[i]; break;
            case 128:     adj_w  = (const float*)d_in[i]; break;
            case 1:       adj_b  = (const float*)d_in[i]; break;
            case 4096:    weight = (const float*)d_in[i]; break;
            case 64:      bias   = (const float*)d_in[i]; break;
            default: break;
        }
    }
    float* out = (float*)d_out;

    gcn_fused<<<GRID, TPB>>>((const float4*)x, adj_w, adj_b,
                             (const float4*)weight, (const float4*)bias, out);
}

// round 13
// speedup vs baseline: 1.0523x; 1.0523x over previous
#include <cuda_runtime.h>

#define GRID 128
#define TPB  512

// cross-kernel scratch (allocation-free rule: __device__ globals).
// Kernel boundaries provide ordering + visibility; no atomics, no fences.
__device__ float g_srow[16384];
__device__ float g_scol[16384];
__device__ float g_Cpart[GRID];
__device__ float g_upart[GRID * 128];

__device__ __forceinline__ float dot4(float4 a, float4 b, float acc) {
    return fmaf(a.x, b.x, fmaf(a.y, b.y, fmaf(a.z, b.z, fmaf(a.w, b.w, acc))));
}

// ---------------------------------------------------------------------------
// k1: row dots. s_col = x_row . adj_w[0:64], s_row = x_row . adj_w[64:128],
// plus per-block partial of sum(s_col). Pure streaming, MLP = 4 x LDG.128.
// ---------------------------------------------------------------------------
__global__ void __launch_bounds__(TPB, 1)
k1_rowdots(const float4* __restrict__ x4, const float* __restrict__ adj_w) {
    const int t    = threadIdx.x;
    const int quad = t & 3;              // 4 lanes per row (16 floats each)
    const int r    = t >> 2;             // 0..127
    const int row  = blockIdx.x * 128 + r;

    const float4* w4 = (const float4*)adj_w;
    float4 wc0 = __ldg(&w4[quad * 4 + 0]), wc1 = __ldg(&w4[quad * 4 + 1]);
    float4 wc2 = __ldg(&w4[quad * 4 + 2]), wc3 = __ldg(&w4[quad * 4 + 3]);
    float4 wr0 = __ldg(&w4[16 + quad * 4 + 0]), wr1 = __ldg(&w4[16 + quad * 4 + 1]);
    float4 wr2 = __ldg(&w4[16 + quad * 4 + 2]), wr3 = __ldg(&w4[16 + quad * 4 + 3]);

    const float4* xr = x4 + (size_t)row * 16 + quad * 4;
    float4 v0 = xr[0], v1 = xr[1], v2 = xr[2], v3 = xr[3];

    float sc = dot4(v3, wc3, dot4(v2, wc2, dot4(v1, wc1, dot4(v0, wc0, 0.f))));
    float sr = dot4(v3, wr3, dot4(v2, wr2, dot4(v1, wr1, dot4(v0, wr0, 0.f))));
    sc += __shfl_xor_sync(0xffffffffu, sc, 1);
    sc += __shfl_xor_sync(0xffffffffu, sc, 2);
    sr += __shfl_xor_sync(0xffffffffu, sr, 1);
    sr += __shfl_xor_sync(0xffffffffu, sr, 2);

    if (quad == 0) {
        g_srow[row] = sr;
        g_scol[row] = sc;
    }

    __shared__ float ws[16];
    float p = (quad == 0) ? sc : 0.f;    // one copy per row
    p += __shfl_xor_sync(0xffffffffu, p, 4);
    p += __shfl_xor_sync(0xffffffffu, p, 8);
    p += __shfl_xor_sync(0xffffffffu, p, 16);
    if ((t & 31) == 0) ws[t >> 5] = p;
    __syncthreads();
    if (t == 0) {
        float s = 0.f;
#pragma unroll
        for (int w = 0; w < 16; w++) s += ws[w];
        g_Cpart[blockIdx.x] = s;
    }
}

// ---------------------------------------------------------------------------
// k2: fold C, compute d per row, accumulate per-block u1/u2 partials.
// x re-read is L2-hot (4 MB working set << 126 MB L2).
// ---------------------------------------------------------------------------
__global__ void __launch_bounds__(TPB, 1)
k2_partials(const float* __restrict__ x, const float* __restrict__ adj_b_p) {
    const int t     = threadIdx.x;
    const int blk   = blockIdx.x;
    const int batch = blk >> 5;          // 32 blocks per batch

    __shared__ float s_d[128], s_w2[128];
    __shared__ float red[1024];

    const float ab = __ldg(adj_b_p);

    if (t < 128) {                       // redundant per-warp C fold
        float p = g_Cpart[batch * 32 + (t & 31)];
        p += __shfl_xor_sync(0xffffffffu, p, 16);
        p += __shfl_xor_sync(0xffffffffu, p, 8);
        p += __shfl_xor_sync(0xffffffffu, p, 4);
        p += __shfl_xor_sync(0xffffffffu, p, 2);
        p += __shfl_xor_sync(0xffffffffu, p, 1);       // C in all lanes
        const float srv = g_srow[blk * 128 + t] + ab;
        const float scv = g_scol[blk * 128 + t];
        const float d = rsqrtf(fmaxf(fmaf(4096.f, srv, p), 1.0f));
        s_d[t]  = d;
        s_w2[t] = scv * d;
    }
    __syncthreads();

    const int f   = t & 63;
    const int sub = t >> 6;              // 8 row-lanes
    const int row0 = blk * 128;
    float a1 = 0.f, a2 = 0.f;
#pragma unroll
    for (int k = 0; k < 16; k++) {
        const int r = sub + (k << 3);
        const float xv = __ldg(&x[(size_t)((row0 + r) << 6) + f]);
        a1 = fmaf(s_d[r],  xv, a1);
        a2 = fmaf(s_w2[r], xv, a2);
    }
    red[t]       = a1;
    red[512 + t] = a2;
    __syncthreads();
    if (t < 128) {                       // fold both halves in one round
        const int which = t >> 6;        // 0: u1, 1: u2
        const int o     = t & 63;
        const float* rp = red + which * 512 + o;
        float s = 0.f;
#pragma unroll
        for (int k = 0; k < 8; k++) s += rp[64 * k];
        g_upart[blk * 128 + which * 64 + o] = s;
    }
}

// ---------------------------------------------------------------------------
// k3: fold u partials (L2-hot), matvec T = u @ W, stream output.
// Weight prefetch has no k2-dependency -> overlaps the fold loads.
// ---------------------------------------------------------------------------
__global__ void __launch_bounds__(TPB, 1)
k3_output(const float4* __restrict__ weight4, const float4* __restrict__ bias4,
          const float* __restrict__ adj_b_p, float* __restrict__ out) {
    const int t     = threadIdx.x;
    const int blk   = blockIdx.x;
    const int batch = blk >> 5;

    __shared__ float sW[4096];
    __shared__ float sB[64];
    __shared__ float s_e1[128], s_d[128];
    __shared__ float red[512];
    __shared__ float su[128], sT[128];

    // weight/bias prefetch (independent of k1/k2 outputs)
    ((float4*)sW)[t]       = weight4[t];
    ((float4*)sW)[512 + t] = weight4[512 + t];
    if (t < 16) ((float4*)sB)[t] = bias4[t];

    const float ab = __ldg(adj_b_p);

    // fold 32 u-partials of this batch: 4096 floats, 8 loads per thread
    {
        const int e  = t & 127;
        const int g4 = t >> 7;           // 4 groups of 8 partials
        float acc = 0.f;
#pragma unroll
        for (int k = 0; k < 8; k++)
            acc += g_upart[(batch * 32 + g4 * 8 + k) * 128 + e];
        // d/e1 for this block's rows (independent of the fold staging)
        if (t < 128) {
            float p = g_Cpart[batch * 32 + (t & 31)];
            p += __shfl_xor_sync(0xffffffffu, p, 16);
            p += __shfl_xor_sync(0xffffffffu, p, 8);
            p += __shfl_xor_sync(0xffffffffu, p, 4);
            p += __shfl_xor_sync(0xffffffffu, p, 2);
            p += __shfl_xor_sync(0xffffffffu, p, 1);
            const float srv = g_srow[blk * 128 + t] + ab;
            const float d = rsqrtf(fmaxf(fmaf(4096.f, srv, p), 1.0f));
            s_e1[t] = d * srv;
            s_d[t]  = d;
        }
        if (t < 256) red[t] = acc;       // stage groups 0,1
        __syncthreads();
        if (t < 128)
            su[t] = red[t] + red[128 + t];
        if (t >= 256) red[t - 256] = acc; // stage groups 2,3 (reuse red)
        __syncthreads();
        if (t < 128)
            su[t] += red[t] + red[128 + t];
        __syncthreads();
    }

    // split-K matvec: 4 threads per (which,o) pair, 16-FMA chains
    {
        const int pair  = t & 127;
        const int which = pair >> 6, o = pair & 63;
        const int split = t >> 7;        // 0..3
        const float* u = &su[which * 64 + split * 16];
        const float* w = &sW[split * 16 * 64 + o];
        float p = 0.f;
#pragma unroll
        for (int ff = 0; ff < 16; ff++)
            p = fmaf(u[ff], w[ff * 64], p);
        red[t] = p;
    }
    __syncthreads();
    if (t < 128)
        sT[t] = (red[t] + red[128 + t]) + (red[256 + t] + red[384 + t]);
    __syncthreads();

    // output: thread t handles row r, 16 consecutive o's (4 float4 stores)
    const int r = t >> 2, q = t & 3;
    const float e1 = s_e1[r];
    const float dd = s_d[r];
    const float4* T1p = (const float4*)&sT[q * 16];
    const float4* T2p = (const float4*)&sT[64 + q * 16];
    const float4* Bp  = (const float4*)&sB[q * 16];
    float4* op = (float4*)&out[(size_t)((blk * 128 + r) << 6) + q * 16];
#pragma unroll
    for (int i = 0; i < 4; i++) {
        const float4 t1 = T1p[i], t2 = T2p[i], bb = Bp[i];
        float4 v;
        v.x = fmaxf(fmaf(e1, t1.x, fmaf(dd, t2.x, bb.x)), 0.f);
        v.y = fmaxf(fmaf(e1, t1.y, fmaf(dd, t2.y, bb.y)), 0.f);
        v.z = fmaxf(fmaf(e1, t1.z, fmaf(dd, t2.z, bb.z)), 0.f);
        v.w = fmaxf(fmaf(e1, t1.w, fmaf(dd, t2.w, bb.w)), 0.f);
        op[i] = v;
    }
}

extern "C" void kernel_launch(void* const* d_in, const int* in_sizes, int n_in,
                              void* d_out, int out_size) {
    const float* x = nullptr;       // 1048576
    const float* adj_w = nullptr;   // 128
    const float* adj_b = nullptr;   // 1
    const float* weight = nullptr;  // 4096
    const float* bias = nullptr;    // 64
    for (int i = 0; i < n_in; i++) {
        switch (in_sizes[i]) {
            case 1048576: x      = (const float*)d_in[i]; break;
            case 128:     adj_w  = (const float*)d_in[i]; break;
            case 1:       adj_b  = (const float*)d_in[i]; break;
            case 4096:    weight = (const float*)d_in[i]; break;
            case 64:      bias   = (const float*)d_in[i]; break;
            default: break;
        }
    }
    float* out = (float*)d_out;

    k1_rowdots<<<GRID, TPB>>>((const float4*)x, adj_w);
    k2_partials<<<GRID, TPB>>>(x, adj_b);
    k3_output<<<GRID, TPB>>>((const float4*)weight, (const float4*)bias, adj_b, out);
}

// round 14
// speedup vs baseline: 1.1633x; 1.1055x over previous
#include <cuda_runtime.h>

#define GRID 128
#define TPB  512

// cross-kernel scratch (allocation-free rule: __device__ globals).
// Kernel boundaries + PDL grid-dependency sync provide ordering/visibility.
__device__ float g_srow[16384];
__device__ float g_scol[16384];
__device__ float g_Cpart[GRID];
__device__ float g_upart[GRID * 128];

__device__ __forceinline__ float dot4(float4 a, float4 b, float acc) {
    return fmaf(a.x, b.x, fmaf(a.y, b.y, fmaf(a.z, b.z, fmaf(a.w, b.w, acc))));
}

// ---------------------------------------------------------------------------
// k1: row dots + per-block C partial. Pure streaming (MLP = 4 x LDG.128).
// Triggers programmatic launch completion after its final global stores.
// ---------------------------------------------------------------------------
__global__ void __launch_bounds__(TPB, 1)
k1_rowdots(const float4* __restrict__ x4, const float* __restrict__ adj_w) {
    const int t    = threadIdx.x;
    const int quad = t & 3;              // 4 lanes per row (16 floats each)
    const int r    = t >> 2;             // 0..127
    const int row  = blockIdx.x * 128 + r;

    const float4* w4 = (const float4*)adj_w;
    float4 wc0 = __ldg(&w4[quad * 4 + 0]), wc1 = __ldg(&w4[quad * 4 + 1]);
    float4 wc2 = __ldg(&w4[quad * 4 + 2]), wc3 = __ldg(&w4[quad * 4 + 3]);
    float4 wr0 = __ldg(&w4[16 + quad * 4 + 0]), wr1 = __ldg(&w4[16 + quad * 4 + 1]);
    float4 wr2 = __ldg(&w4[16 + quad * 4 + 2]), wr3 = __ldg(&w4[16 + quad * 4 + 3]);

    const float4* xr = x4 + (size_t)row * 16 + quad * 4;
    float4 v0 = xr[0], v1 = xr[1], v2 = xr[2], v3 = xr[3];

    float sc = dot4(v3, wc3, dot4(v2, wc2, dot4(v1, wc1, dot4(v0, wc0, 0.f))));
    float sr = dot4(v3, wr3, dot4(v2, wr2, dot4(v1, wr1, dot4(v0, wr0, 0.f))));
    sc += __shfl_xor_sync(0xffffffffu, sc, 1);
    sc += __shfl_xor_sync(0xffffffffu, sc, 2);
    sr += __shfl_xor_sync(0xffffffffu, sr, 1);
    sr += __shfl_xor_sync(0xffffffffu, sr, 2);

    if (quad == 0) {
        g_srow[row] = sr;
        g_scol[row] = sc;
    }

    __shared__ float ws[16];
    float p = (quad == 0) ? sc : 0.f;    // one copy per row
    p += __shfl_xor_sync(0xffffffffu, p, 4);
    p += __shfl_xor_sync(0xffffffffu, p, 8);
    p += __shfl_xor_sync(0xffffffffu, p, 16);
    if ((t & 31) == 0) ws[t >> 5] = p;
    __syncthreads();
    if (t == 0) {
        float s = 0.f;
#pragma unroll
        for (int w = 0; w < 16; w++) s += ws[w];
        g_Cpart[blockIdx.x] = s;
    }
    cudaTriggerProgrammaticLaunchCompletion();
}

// ---------------------------------------------------------------------------
// k2: INDEPENDENT x loads first (overlap k1 via PDL), then grid-dep sync,
// then C fold, d per row, u1/u2 partials.
// ---------------------------------------------------------------------------
__global__ void __launch_bounds__(TPB, 1)
k2_partials(const float* __restrict__ x, const float* __restrict__ adj_b_p) {
    const int t     = threadIdx.x;
    const int blk   = blockIdx.x;
    const int batch = blk >> 5;          // 32 blocks per batch

    __shared__ float s_d[128], s_w2[128];
    __shared__ float red[1024];

    // ---- prologue: everything independent of k1 ----
    const float ab = __ldg(adj_b_p);
    const int f   = t & 63;
    const int sub = t >> 6;              // 8 row-lanes
    const int row0 = blk * 128;
    float xv[16];
#pragma unroll
    for (int k = 0; k < 16; k++)
        xv[k] = __ldg(&x[(size_t)((row0 + sub + (k << 3)) << 6) + f]);

    // ---- dependency: k1's srow/scol/Cpart ----
    cudaGridDependencySynchronize();

    if (t < 128) {                       // redundant per-warp C fold
        float p = g_Cpart[batch * 32 + (t & 31)];
        p += __shfl_xor_sync(0xffffffffu, p, 16);
        p += __shfl_xor_sync(0xffffffffu, p, 8);
        p += __shfl_xor_sync(0xffffffffu, p, 4);
        p += __shfl_xor_sync(0xffffffffu, p, 2);
        p += __shfl_xor_sync(0xffffffffu, p, 1);       // C in all lanes
        const float srv = g_srow[blk * 128 + t] + ab;
        const float scv = g_scol[blk * 128 + t];
        const float d = rsqrtf(fmaxf(fmaf(4096.f, srv, p), 1.0f));
        s_d[t]  = d;
        s_w2[t] = scv * d;
    }
    __syncthreads();

    float a1 = 0.f, a2 = 0.f;
#pragma unroll
    for (int k = 0; k < 16; k++) {
        const int r = sub + (k << 3);
        a1 = fmaf(s_d[r],  xv[k], a1);
        a2 = fmaf(s_w2[r], xv[k], a2);
    }
    red[t]       = a1;
    red[512 + t] = a2;
    __syncthreads();
    if (t < 128) {                       // fold both halves in one round
        const int which = t >> 6;        // 0: u1, 1: u2
        const int o     = t & 63;
        const float* rp = red + which * 512 + o;
        float s = 0.f;
#pragma unroll
        for (int k = 0; k < 8; k++) s += rp[64 * k];
        g_upart[blk * 128 + which * 64 + o] = s;
    }
    cudaTriggerProgrammaticLaunchCompletion();
}

// ---------------------------------------------------------------------------
// k3: INDEPENDENT weight/bias prefetch first (overlap k2 via PDL), then
// grid-dep sync, then u fold, matvec T, stream output.
// ---------------------------------------------------------------------------
__global__ void __launch_bounds__(TPB, 1)
k3_output(const float4* __restrict__ weight4, const float4* __restrict__ bias4,
          const float* __restrict__ adj_b_p, float* __restrict__ out) {
    const int t     = threadIdx.x;
    const int blk   = blockIdx.x;
    const int batch = blk >> 5;

    __shared__ float sW[4096];
    __shared__ float sB[64];
    __shared__ float s_e1[128], s_d[128];
    __shared__ float red[512];
    __shared__ float su[128], sT[128];

    // ---- prologue: independent of k1/k2 ----
    ((float4*)sW)[t]       = weight4[t];
    ((float4*)sW)[512 + t] = weight4[512 + t];
    if (t < 16) ((float4*)sB)[t] = bias4[t];
    const float ab = __ldg(adj_b_p);

    // ---- dependency: k2's uparts (and k1's srow/Cpart via k2's sync) ----
    cudaGridDependencySynchronize();

    // fold 32 u-partials of this batch: 4096 floats, 8 loads per thread
    {
        const int e  = t & 127;
        const int g4 = t >> 7;           // 4 groups of 8 partials
        float acc = 0.f;
#pragma unroll
        for (int k = 0; k < 8; k++)
            acc += g_upart[(batch * 32 + g4 * 8 + k) * 128 + e];
        // d/e1 for this block's rows (independent of the fold staging)
        if (t < 128) {
            float p = g_Cpart[batch * 32 + (t & 31)];
            p += __shfl_xor_sync(0xffffffffu, p, 16);
            p += __shfl_xor_sync(0xffffffffu, p, 8);
            p += __shfl_xor_sync(0xffffffffu, p, 4);
            p += __shfl_xor_sync(0xffffffffu, p, 2);
            p += __shfl_xor_sync(0xffffffffu, p, 1);
            const float srv = g_srow[blk * 128 + t] + ab;
            const float d = rsqrtf(fmaxf(fmaf(4096.f, srv, p), 1.0f));
            s_e1[t] = d * srv;
            s_d[t]  = d;
        }
        if (t < 256) red[t] = acc;       // stage groups 0,1
        __syncthreads();
        if (t < 128)
            su[t] = red[t] + red[128 + t];
        if (t >= 256) red[t - 256] = acc; // stage groups 2,3 (reuse red)
        __syncthreads();
        if (t < 128)
            su[t] += red[t] + red[128 + t];
        __syncthreads();
    }

    // split-K matvec: 4 threads per (which,o) pair, 16-FMA chains
    {
        const int pair  = t & 127;
        const int which = pair >> 6, o = pair & 63;
        const int split = t >> 7;        // 0..3
        const float* u = &su[which * 64 + split * 16];
        const float* w = &sW[split * 16 * 64 + o];
        float p = 0.f;
#pragma unroll
        for (int ff = 0; ff < 16; ff++)
            p = fmaf(u[ff], w[ff * 64], p);
        red[t] = p;
    }
    __syncthreads();
    if (t < 128)
        sT[t] = (red[t] + red[128 + t]) + (red[256 + t] + red[384 + t]);
    __syncthreads();

    // output: thread t handles row r, 16 consecutive o's (4 float4 stores)
    const int r = t >> 2, q = t & 3;
    const float e1 = s_e1[r];
    const float dd = s_d[r];
    const float4* T1p = (const float4*)&sT[q * 16];
    const float4* T2p = (const float4*)&sT[64 + q * 16];
    const float4* Bp  = (const float4*)&sB[q * 16];
    float4* op = (float4*)&out[(size_t)((blk * 128 + r) << 6) + q * 16];
#pragma unroll
    for (int i = 0; i < 4; i++) {
        const float4 t1 = T1p[i], t2 = T2p[i], bb = Bp[i];
        float4 v;
        v.x = fmaxf(fmaf(e1, t1.x, fmaf(dd, t2.x, bb.x)), 0.f);
        v.y = fmaxf(fmaf(e1, t1.y, fmaf(dd, t2.y, bb.y)), 0.f);
        v.z = fmaxf(fmaf(e1, t1.z, fmaf(dd, t2.z, bb.z)), 0.f);
        v.w = fmaxf(fmaf(e1, t1.w, fmaf(dd, t2.w, bb.w)), 0.f);
        op[i] = v;
    }
}

extern "C" void kernel_launch(void* const* d_in, const int* in_sizes, int n_in,
                              void* d_out, int out_size) {
    const float* x = nullptr;       // 1048576
    const float* adj_w = nullptr;   // 128
    const float* adj_b = nullptr;   // 1
    const float* weight = nullptr;  // 4096
    const float* bias = nullptr;    // 64
    for (int i = 0; i < n_in; i++) {
        switch (in_sizes[i]) {
            case 1048576: x      = (const float*)d_in[i]; break;
            case 128:     adj_w  = (const float*)d_in[i]; break;
            case 1:       adj_b  = (const float*)d_in[i]; break;
            case 4096:    weight = (const float*)d_in[i]; break;
            case 64:      bias   = (const float*)d_in[i]; break;
            default: break;
        }
    }
    float* out = (float*)d_out;

    // k1: normal launch
    k1_rowdots<<<GRID, TPB>>>((const float4*)x, adj_w);

    // k2, k3: programmatic dependent launches (prologue overlaps predecessor)
    cudaLaunchAttribute attrs[1];
    attrs[0].id = cudaLaunchAttributeProgrammaticStreamSerialization;
    attrs[0].val.programmaticStreamSerializationAllowed = 1;

    cudaLaunchConfig_t cfg = {};
    cfg.gridDim  = dim3(GRID, 1, 1);
    cfg.blockDim = dim3(TPB, 1, 1);
    cfg.dynamicSmemBytes = 0;
    cfg.stream = (cudaStream_t)0;     // legacy default stream (harness captures it)
    cfg.attrs = attrs;
    cfg.numAttrs = 1;

    cudaLaunchKernelEx(&cfg, k2_partials, x, adj_b);
    cudaLaunchKernelEx(&cfg, k3_output,
                       (const float4*)weight, (const float4*)bias, adj_b, out);
}